// round 1
// baseline (speedup 1.0000x reference)
#include <cuda_runtime.h>
#include <cuda_bf16.h>
#include <cstdint>

// AxonalConnections: out[b,t] = sum_s adj[t,s] * (1.5*E[s]-0.5) * spikes[b,s]
// adj is conv-pattern sparse: for each target t=(ti,tj), only the 9 sources
// s=(ti-1+ki, tj-1+kj), ki,kj in {0,1,2}, are nonzero (boundary-clipped).
// We gather exactly those 9 weights per target, fold the E modulation into
// them once, and run a 9-tap FMA per (target, batch).

#define HW 128
#define S_TOT (HW * HW)      // 16384
#define B_TOT 32
#define B_PER_BLOCK 8        // grid.y = 4 batch groups
#define THREADS 128

__global__ __launch_bounds__(THREADS)
void axonal_sparse_kernel(const float* __restrict__ spikes,   // [B, 128, 128]
                          const float* __restrict__ E,        // [128, 128]
                          const float* __restrict__ adj,      // [16384, 16384]
                          float* __restrict__ out)            // [B, 128, 128]
{
    const int t  = blockIdx.x * THREADS + threadIdx.x;  // target index 0..16383
    const int ti = t >> 7;
    const int tj = t & 127;

    // Gather the 9 (possibly clipped) weights for this target row and fold in
    // the excitatory/inhibitory modulation of the SOURCE neuron.
    float f[9];
    int   soff[9];
    const size_t row = (size_t)t * S_TOT;
#pragma unroll
    for (int k = 0; k < 9; ++k) {
        const int ki = k / 3, kj = k - 3 * (k / 3);
        const int si = ti - 1 + ki;
        const int sj = tj - 1 + kj;
        const bool ok = (si >= 0) & (si < HW) & (sj >= 0) & (sj < HW);
        const int s = si * HW + sj;
        soff[k] = ok ? s : 0;                    // safe dummy index when clipped
        if (ok) {
            const float w = __ldg(&adj[row + (size_t)s]);
            const float e = __ldg(&E[s]);
            f[k] = w * (1.5f * e - 0.5f);
        } else {
            f[k] = 0.0f;                         // clipped taps contribute 0
        }
    }

    const int b0 = blockIdx.y * B_PER_BLOCK;
#pragma unroll
    for (int bb = 0; bb < B_PER_BLOCK; ++bb) {
        const int b = b0 + bb;
        const float* __restrict__ sp = spikes + (size_t)b * S_TOT;
        float acc = 0.0f;
#pragma unroll
        for (int k = 0; k < 9; ++k)
            acc = fmaf(f[k], __ldg(&sp[soff[k]]), acc);
        out[(size_t)b * S_TOT + t] = acc;
    }
}

extern "C" void kernel_launch(void* const* d_in, const int* in_sizes, int n_in,
                              void* d_out, int out_size)
{
    // Identify inputs by element count (defensive against ordering):
    //   spikes:    32*128*128   = 524288
    //   E:         128*128      = 16384
    //   adjacency: 16384*16384  = 268435456
    const float* spikes = nullptr;
    const float* E      = nullptr;
    const float* adj    = nullptr;
    for (int i = 0; i < n_in; ++i) {
        if (in_sizes[i] == B_TOT * S_TOT)       spikes = (const float*)d_in[i];
        else if (in_sizes[i] == S_TOT)          E      = (const float*)d_in[i];
        else                                    adj    = (const float*)d_in[i];
    }
    float* out = (float*)d_out;

    dim3 grid(S_TOT / THREADS, B_TOT / B_PER_BLOCK);  // (128, 4) = 512 CTAs
    axonal_sparse_kernel<<<grid, THREADS>>>(spikes, E, adj, out);
}

// round 2
// speedup vs baseline: 1.0895x; 1.0895x over previous
#include <cuda_runtime.h>
#include <cuda_bf16.h>
#include <cstdint>

// AxonalConnections: out[b,t] = sum_s adj[t,s] * (1.5*E[s]-0.5) * spikes[b,s]
// adj is conv-pattern sparse (9 taps per target, boundary-clipped).
//
// R2 structure: each CTA owns 32 consecutive targets and ALL 32 batches.
//   Phase 1: 288 threads gather+fold the 32x9 weights into smem (adj read
//            exactly once across the whole grid -> minimal scattered traffic).
//   Phase 2: 512 threads = 32 targets x 16 batch-groups; every warp covers
//            32 consecutive targets -> fully coalesced spike loads + stores,
//            broadcast conflict-free smem weight reads.

#define HW 128
#define S_TOT (HW * HW)      // 16384
#define B_TOT 32
#define TPC 32               // targets per CTA
#define THREADS 512          // 16 warps: 32 targets x 16 batch groups
#define NSLOT (TPC * 9)      // 288 gather slots

__global__ __launch_bounds__(THREADS)
void axonal_smem_kernel(const float* __restrict__ spikes,   // [B, 16384]
                        const float* __restrict__ E,        // [16384]
                        const float* __restrict__ adj,      // [16384, 16384]
                        float* __restrict__ out)            // [B, 16384]
{
    __shared__ float wsm[NSLOT];   // [k][tloc] folded weights
    __shared__ int   ssm[NSLOT];   // [k][tloc] clamped source indices

    const int tid = threadIdx.x;
    const int t0  = blockIdx.x * TPC;

    // ---- Phase 1: gather + fold 9 weights per target into smem ----
    if (tid < NSLOT) {
        const int tloc = tid & (TPC - 1);      // consecutive lanes -> consecutive banks
        const int k    = tid / TPC;            // 0..8
        const int t    = t0 + tloc;
        const int ti   = t >> 7;
        const int tj   = t & (HW - 1);
        const int ki   = k / 3;
        const int kj   = k - 3 * ki;
        const int si   = ti - 1 + ki;
        const int sj   = tj - 1 + kj;
        const bool ok  = (si >= 0) & (si < HW) & (sj >= 0) & (sj < HW);
        const int s    = si * HW + sj;
        float w = 0.0f;
        if (ok) {
            w = __ldg(&adj[(size_t)t * S_TOT + (size_t)s]) *
                (1.5f * __ldg(&E[s]) - 0.5f);
        }
        wsm[k * TPC + tloc] = w;
        ssm[k * TPC + tloc] = ok ? s : 0;
    }
    __syncthreads();

    // ---- Phase 2: 9-tap FMA per (target, batch) ----
    const int tloc = tid & (TPC - 1);   // lane id -> coalesced across warp
    const int bg   = tid >> 5;          // 0..15, two batches each
    const int t    = t0 + tloc;

    float w[9];
    int   so[9];
#pragma unroll
    for (int k = 0; k < 9; ++k) {
        w[k]  = wsm[k * TPC + tloc];    // broadcast across the 16 warps
        so[k] = ssm[k * TPC + tloc];
    }

#pragma unroll
    for (int bb = 0; bb < 2; ++bb) {
        const int b = bg * 2 + bb;
        const float* __restrict__ sp = spikes + (size_t)b * S_TOT;
        // 3 accumulators to shorten the dependent-FMA chain
        float a0 = w[0] * __ldg(&sp[so[0]]);
        float a1 = w[1] * __ldg(&sp[so[1]]);
        float a2 = w[2] * __ldg(&sp[so[2]]);
        a0 = fmaf(w[3], __ldg(&sp[so[3]]), a0);
        a1 = fmaf(w[4], __ldg(&sp[so[4]]), a1);
        a2 = fmaf(w[5], __ldg(&sp[so[5]]), a2);
        a0 = fmaf(w[6], __ldg(&sp[so[6]]), a0);
        a1 = fmaf(w[7], __ldg(&sp[so[7]]), a1);
        a2 = fmaf(w[8], __ldg(&sp[so[8]]), a2);
        out[(size_t)b * S_TOT + t] = a0 + a1 + a2;
    }
}

extern "C" void kernel_launch(void* const* d_in, const int* in_sizes, int n_in,
                              void* d_out, int out_size)
{
    // Identify inputs by element count:
    //   spikes: 524288, E: 16384, adjacency: 268435456
    const float* spikes = nullptr;
    const float* E      = nullptr;
    const float* adj    = nullptr;
    for (int i = 0; i < n_in; ++i) {
        if (in_sizes[i] == B_TOT * S_TOT)  spikes = (const float*)d_in[i];
        else if (in_sizes[i] == S_TOT)     E      = (const float*)d_in[i];
        else                               adj    = (const float*)d_in[i];
    }
    float* out = (float*)d_out;

    axonal_smem_kernel<<<S_TOT / TPC, THREADS>>>(spikes, E, adj, out);  // 512 CTAs
}

// round 3
// speedup vs baseline: 1.3527x; 1.2415x over previous
#include <cuda_runtime.h>
#include <cuda_bf16.h>
#include <cstdint>

// AxonalConnections: out[b,t] = sum_s adj[t,s] * (1.5*E[s]-0.5) * spikes[b,s]
// adj is conv-pattern sparse (9 taps per target, boundary-clipped).
//
// R3: 256 CTAs (single resident wave, no tail), 64 targets per CTA.
//   Phase 1: 192 threads; each loads the 3 ADJACENT taps of one ki-row
//            (guaranteed sector dedup, MLP=3), folds E, writes smem.
//   Phase 2: 512 threads = 64 targets x 8 batch-groups x 4 batches each,
//            fully unrolled -> 36 independent coalesced spike loads/thread.

#define HW 128
#define S_TOT (HW * HW)      // 16384
#define B_TOT 32
#define TPC 64               // targets per CTA
#define THREADS 512
#define NSLOT (TPC * 9)      // 576

__global__ __launch_bounds__(THREADS)
void axonal_r3_kernel(const float* __restrict__ spikes,   // [B, 16384]
                      const float* __restrict__ E,        // [16384]
                      const float* __restrict__ adj,      // [16384, 16384]
                      float* __restrict__ out)            // [B, 16384]
{
    __shared__ float wsm[NSLOT];   // [k][tloc] folded weights
    __shared__ int   ssm[NSLOT];   // [k][tloc] safe source indices

    const int tid = threadIdx.x;
    const int t0  = blockIdx.x * TPC;

    // ---- Phase 1: per-thread 3-tap row gather (adjacent addresses) ----
    if (tid < TPC * 3) {
        const int tloc = tid & (TPC - 1);
        const int ki   = tid >> 6;             // 0..2
        const int t    = t0 + tloc;
        const int ti   = t >> 7;
        const int tj   = t & (HW - 1);
        const int si   = ti - 1 + ki;
        const bool rowok = (si >= 0) & (si < HW);
        const size_t rowbase = (size_t)t * S_TOT + (size_t)(si * HW);
#pragma unroll
        for (int kj = 0; kj < 3; ++kj) {
            const int sj = tj - 1 + kj;
            const bool ok = rowok & (sj >= 0) & (sj < HW);
            const int s  = si * HW + sj;
            float w = 0.0f;
            if (ok) {
                w = __ldg(&adj[rowbase + (size_t)sj]) *
                    (1.5f * __ldg(&E[s]) - 0.5f);
            }
            const int k = ki * 3 + kj;
            wsm[k * TPC + tloc] = w;
            ssm[k * TPC + tloc] = ok ? s : 0;
        }
    }
    __syncthreads();

    // ---- Phase 2: 9-tap FMA per (target, batch), 4 batches per thread ----
    const int tloc = tid & (TPC - 1);   // lanes consecutive -> coalesced
    const int bg   = tid >> 6;          // 0..7 batch groups
    const int t    = t0 + tloc;

    float w[9];
    int   so[9];
#pragma unroll
    for (int k = 0; k < 9; ++k) {
        w[k]  = wsm[k * TPC + tloc];
        so[k] = ssm[k * TPC + tloc];
    }

#pragma unroll
    for (int bb = 0; bb < 4; ++bb) {
        const int b = bg * 4 + bb;
        const float* __restrict__ sp = spikes + (size_t)b * S_TOT;
        float a0 = w[0] * __ldg(&sp[so[0]]);
        float a1 = w[1] * __ldg(&sp[so[1]]);
        float a2 = w[2] * __ldg(&sp[so[2]]);
        a0 = fmaf(w[3], __ldg(&sp[so[3]]), a0);
        a1 = fmaf(w[4], __ldg(&sp[so[4]]), a1);
        a2 = fmaf(w[5], __ldg(&sp[so[5]]), a2);
        a0 = fmaf(w[6], __ldg(&sp[so[6]]), a0);
        a1 = fmaf(w[7], __ldg(&sp[so[7]]), a1);
        a2 = fmaf(w[8], __ldg(&sp[so[8]]), a2);
        out[(size_t)b * S_TOT + t] = a0 + a1 + a2;
    }
}

extern "C" void kernel_launch(void* const* d_in, const int* in_sizes, int n_in,
                              void* d_out, int out_size)
{
    // Identify inputs by element count:
    //   spikes: 524288, E: 16384, adjacency: 268435456
    const float* spikes = nullptr;
    const float* E      = nullptr;
    const float* adj    = nullptr;
    for (int i = 0; i < n_in; ++i) {
        if (in_sizes[i] == B_TOT * S_TOT)  spikes = (const float*)d_in[i];
        else if (in_sizes[i] == S_TOT)     E      = (const float*)d_in[i];
        else                               adj    = (const float*)d_in[i];
    }
    float* out = (float*)d_out;

    axonal_r3_kernel<<<S_TOT / TPC, THREADS>>>(spikes, E, adj, out);  // 256 CTAs
}